// round 2
// baseline (speedup 1.0000x reference)
#include <cuda_runtime.h>
#include <cstdint>

#define NN   2000
#define HH   4
#define NDm  64
#define KK   20
#define TILE 8
#define BLT  128          // B*L = 4*32
#define DD   64
#define OUT_ELEMS (4*2000*32*64)
#define NNZ_CAP   (NN*80)

// ---------------- scratch (device globals; no allocation) ----------------
__device__ float g_support[(size_t)BLT*NN*DD];   // 65.5 MB
__device__ int   g_tki[HH*NN*KK];
__device__ float g_tkv[HH*NN*KK];
__device__ int   g_rowj[NN*80];
__device__ float g_rowv[NN*80];
__device__ int   g_rowcnt[NN];
__device__ int   g_colcnt[NN];
__device__ int   g_colptr[NN];
__device__ int   g_colcur[NN];
__device__ int   g_ci[NNZ_CAP];
__device__ float g_cv[NNZ_CAP];
__device__ float g_fa_fb[(size_t)NN*NN];         // fallback final_adj (16 MB)

// ---------------- 0: zero counters + final_adj region ----------------
__global__ void zero_kernel(float* fa) {
    int idx = blockIdx.x * blockDim.x + threadIdx.x;
    if (idx < NN) g_colcnt[idx] = 0;
    size_t stride = (size_t)gridDim.x * blockDim.x;
    for (size_t p = idx; p < (size_t)NN * NN; p += stride) fa[p] = 0.f;
}

// ---------------- 1: scores + softmax + top-20 ----------------
// grid = H * (N/TILE) blocks, 256 threads (8 warps; warp w owns row n0+w)
__global__ __launch_bounds__(256) void scores_topk_kernel(
    const float* __restrict__ e1, const float* __restrict__ e2,
    const float* __restrict__ temp)
{
    extern __shared__ float sm[];
    float* s   = sm;                // [TILE][NN]
    float* e1s = sm + TILE * NN;    // [TILE][NDm]

    int h  = blockIdx.x / (NN / TILE);
    int n0 = (blockIdx.x % (NN / TILE)) * TILE;
    int tid = threadIdx.x;

    for (int i = tid; i < TILE * NDm; i += blockDim.x)
        e1s[i] = e1[((size_t)h * NN + n0 + i / NDm) * NDm + (i % NDm)];
    __syncthreads();

    for (int m = tid; m < NN; m += blockDim.x) {
        float acc[TILE];
#pragma unroll
        for (int r = 0; r < TILE; r++) acc[r] = 0.f;
        const float* e2p = e2 + (size_t)h * NDm * NN + m;
#pragma unroll 8
        for (int d = 0; d < NDm; d++) {
            float b = e2p[(size_t)d * NN];
#pragma unroll
            for (int r = 0; r < TILE; r++) acc[r] = fmaf(e1s[r * NDm + d], b, acc[r]);
        }
#pragma unroll
        for (int r = 0; r < TILE; r++) s[r * NN + m] = acc[r];
    }
    __syncthreads();

    int w = tid >> 5, lane = tid & 31;
    float invT = 1.0f / temp[h];
    float* sw = s + w * NN;

    // relu + /temp in place; row max (all values >= 0)
    float M = 0.f;
    for (int m = lane; m < NN; m += 32) {
        float a = fmaxf(sw[m], 0.f) * invT;
        sw[m] = a;
        M = fmaxf(M, a);
    }
#pragma unroll
    for (int o = 16; o; o >>= 1) M = fmaxf(M, __shfl_xor_sync(0xffffffffu, M, o));

    float S = 0.f;
    for (int m = lane; m < NN; m += 32) S += __expf(sw[m] - M);
#pragma unroll
    for (int o = 16; o; o >>= 1) S += __shfl_xor_sync(0xffffffffu, S, o);

    int base = (h * NN + n0 + w) * KK;
    float ssel = 0.f;
    for (int k = 0; k < KK; k++) {
        float best = -1.f; int bi = NN;
        for (int m = lane; m < NN; m += 32) {
            float v = sw[m];
            if (v > best) { best = v; bi = m; }   // ascending m keeps lowest index on ties
        }
#pragma unroll
        for (int o = 16; o; o >>= 1) {
            float ov = __shfl_xor_sync(0xffffffffu, best, o);
            int   oi = __shfl_xor_sync(0xffffffffu, bi,   o);
            if (ov > best || (ov == best && oi < bi)) { best = ov; bi = oi; }
        }
        float e = __expf(best - M);
        ssel += e;                       // same on all lanes
        if (lane == 0) { g_tki[base + k] = bi; g_tkv[base + k] = e; }
        sw[bi] = -1.f;                   // mark taken (all lanes write same value)
        __syncwarp();
    }
    // adj_val = (e/S) / (ssel/S + 1e-8) = e / (ssel + 1e-8*S)
    float denom = ssel + 1e-8f * S;
    __syncwarp();
    if (lane < KK) g_tkv[base + lane] = g_tkv[base + lane] / denom;
}

// ---------------- 2: per-row union + edge MLP -> sparse rows + dense fa ----------------
// one warp per row i; grid = N/8 blocks of 256 threads
__global__ __launch_bounds__(256) void build_rows_kernel(
    const float* __restrict__ ew1, const float* __restrict__ eb1,
    const float* __restrict__ ew2, const float* __restrict__ eb2,
    float* __restrict__ fa)
{
    __shared__ float s_ew1[HH * 8];
    __shared__ float s_eb1[8];
    __shared__ float s_ew2[8];
    __shared__ int   s_js[8][80];
    __shared__ float s_vs[8][80];

    int tid = threadIdx.x;
    if (tid < 32) s_ew1[tid] = ew1[tid];
    else if (tid < 40) s_eb1[tid - 32] = eb1[tid - 32];
    else if (tid < 48) s_ew2[tid - 40] = ew2[tid - 40];
    float beta2 = eb2[0];
    __syncthreads();

    int w = tid >> 5, lane = tid & 31;
    int i = blockIdx.x * 8 + w;

    for (int e = lane; e < 80; e += 32) {
        int hh = e / KK, k = e % KK;
        s_js[w][e] = g_tki[(hh * NN + i) * KK + k];
        s_vs[w][e] = g_tkv[(hh * NN + i) * KK + k];
    }
    __syncwarp();

    int cnt = 0;
    for (int p = 0; p < 3; p++) {
        int e = lane + p * 32;
        bool owned = false;
        int j = -1;
        if (e < 80) {
            j = s_js[w][e];
            owned = true;
            for (int q = 0; q < e; q++)
                if (s_js[w][q] == j) { owned = false; break; }
        }
        unsigned bal = __ballot_sync(0xffffffffu, owned);
        int pos = cnt + __popc(bal & ((1u << lane) - 1u));
        if (owned) {
            float v[HH];
            float vsum = 0.f;
#pragma unroll
            for (int hh = 0; hh < HH; hh++) {
                float vv = 0.f;
                for (int k = 0; k < KK; k++)
                    if (s_js[w][hh * KK + k] == j) { vv = s_vs[w][hh * KK + k]; break; }
                v[hh] = vv; vsum += vv;
            }
            float ewv = beta2;
#pragma unroll
            for (int c = 0; c < 8; c++) {
                float hid = s_eb1[c];
#pragma unroll
                for (int hh = 0; hh < HH; hh++) hid = fmaf(v[hh], s_ew1[hh * 8 + c], hid);
                hid = fmaxf(hid, 0.f);
                ewv = fmaf(hid, s_ew2[c], ewv);
            }
            float sig  = 1.f / (1.f + __expf(-ewv));
            float favv = sig * (vsum * 0.25f);
            g_rowj[i * 80 + pos] = j;
            g_rowv[i * 80 + pos] = favv;
            atomicAdd(&g_colcnt[j], 1);
            fa[(size_t)i * NN + j] = favv;
        }
        cnt += __popc(bal);
    }
    if (lane == 0) g_rowcnt[i] = cnt;
}

// ---------------- 3: exclusive scan over column counts (single block) ----------------
__global__ __launch_bounds__(1024) void scan_kernel() {
    __shared__ int buf[1024];
    int t = threadIdx.x;
    int c0 = (2 * t     < NN) ? g_colcnt[2 * t]     : 0;
    int c1 = (2 * t + 1 < NN) ? g_colcnt[2 * t + 1] : 0;
    int psum = c0 + c1;
    buf[t] = psum;
    __syncthreads();
    for (int off = 1; off < 1024; off <<= 1) {
        int tmp = (t >= off) ? buf[t - off] : 0;
        __syncthreads();
        buf[t] += tmp;
        __syncthreads();
    }
    int base = buf[t] - psum;   // exclusive
    if (2 * t < NN)     { g_colptr[2 * t]     = base;      g_colcur[2 * t]     = base; }
    if (2 * t + 1 < NN) { g_colptr[2 * t + 1] = base + c0; g_colcur[2 * t + 1] = base + c0; }
}

// ---------------- 4: fill transposed (per-column) entry lists ----------------
__global__ void fill_kernel() {
    int i = blockIdx.x;
    int t = threadIdx.x;
    int cnt = g_rowcnt[i];
    if (t < cnt) {
        int j = g_rowj[i * 80 + t];
        int pos = atomicAdd(&g_colcur[j], 1);
        g_ci[pos] = i;
        g_cv[pos] = g_rowv[i * 80 + t];
    }
}

// ---------------- 5: support = xr @ W  (B*L x N x 64) ----------------
// block = 256 threads, 16 rows/block
__global__ __launch_bounds__(256) void support_kernel(
    const float* __restrict__ x, const float* __restrict__ W)
{
    __shared__ float Ws[64 * 64];
    __shared__ float xs[16 * 64];
    int tid = threadIdx.x;
    for (int i = tid; i < 4096; i += 256) Ws[i] = W[i];
    int row0 = blockIdx.x * 16;
    for (int i = tid; i < 16 * 64; i += 256) {
        int rr = i >> 6, d = i & 63;
        int r = row0 + rr;           // r = bl*NN + n
        int bl = r / NN, n = r % NN;
        int b = bl >> 5, l = bl & 31;
        xs[i] = x[(((size_t)(b * NN + n) * 32) + l) * 64 + d];
    }
    __syncthreads();
    int o = tid & 63, rq = tid >> 6;
    float a0 = 0.f, a1 = 0.f, a2 = 0.f, a3 = 0.f;
#pragma unroll 8
    for (int d = 0; d < 64; d++) {
        float wv = Ws[d * 64 + o];
        a0 = fmaf(xs[(rq * 4 + 0) * 64 + d], wv, a0);
        a1 = fmaf(xs[(rq * 4 + 1) * 64 + d], wv, a1);
        a2 = fmaf(xs[(rq * 4 + 2) * 64 + d], wv, a2);
        a3 = fmaf(xs[(rq * 4 + 3) * 64 + d], wv, a3);
    }
    size_t base = (size_t)(row0 + rq * 4) * 64 + o;
    g_support[base]       = a0;
    g_support[base + 64]  = a1;
    g_support[base + 128] = a2;
    g_support[base + 192] = a3;
}

// ---------------- 6: sparse out[b,c,l,:] = sum_e w_e * support[bl, j_e, :] + bias ----------------
// one block per column c; 256 threads = 16 float4-lanes x 16 bl-groups; 8 bl iters
__global__ __launch_bounds__(256) void spmm_kernel(
    const float* __restrict__ bias, float* __restrict__ out)
{
    __shared__ int   sj[512];
    __shared__ float sv[512];
    int c = blockIdx.x;
    int tid = threadIdx.x;
    int q = tid & 15;       // d = 4q .. 4q+3
    int g = tid >> 4;       // 0..15
    int start = g_colptr[c], cnt = g_colcnt[c];

    float4 acc[8];
#pragma unroll
    for (int it = 0; it < 8; it++) acc[it] = make_float4(0.f, 0.f, 0.f, 0.f);

    for (int off = 0; off < cnt; off += 512) {
        int chunk = min(512, cnt - off);
        for (int e = tid; e < chunk; e += 256) {
            sj[e] = g_ci[start + off + e];
            sv[e] = g_cv[start + off + e];
        }
        __syncthreads();
        for (int e = 0; e < chunk; e++) {
            float wv = sv[e];
            const float4* sp = (const float4*)g_support + (size_t)sj[e] * 16 + q;
#pragma unroll
            for (int it = 0; it < 8; it++) {
                int bl = it * 16 + g;
                float4 s4 = sp[(size_t)bl * (NN * 16)];
                acc[it].x = fmaf(wv, s4.x, acc[it].x);
                acc[it].y = fmaf(wv, s4.y, acc[it].y);
                acc[it].z = fmaf(wv, s4.z, acc[it].z);
                acc[it].w = fmaf(wv, s4.w, acc[it].w);
            }
        }
        __syncthreads();
    }

    float4 bv = ((const float4*)bias)[q];
#pragma unroll
    for (int it = 0; it < 8; it++) {
        int bl = it * 16 + g;
        int b = bl >> 5, l = bl & 31;
        float4 r;
        r.x = acc[it].x + bv.x;
        r.y = acc[it].y + bv.y;
        r.z = acc[it].z + bv.z;
        r.w = acc[it].w + bv.w;
        ((float4*)out)[(size_t)((b * NN + c) * 32 + l) * 16 + q] = r;
    }
}

// ---------------- launch ----------------
extern "C" void kernel_launch(void* const* d_in, const int* in_sizes, int n_in,
                              void* d_out, int out_size)
{
    const float* x      = (const float*)d_in[0];
    const float* e1     = (const float*)d_in[1];
    const float* e2     = (const float*)d_in[2];
    const float* temp   = (const float*)d_in[3];
    const float* ew1    = (const float*)d_in[4];
    const float* eb1    = (const float*)d_in[5];
    const float* ew2    = (const float*)d_in[6];
    const float* eb2    = (const float*)d_in[7];
    const float* weight = (const float*)d_in[8];
    const float* bias   = (const float*)d_in[9];
    float* out = (float*)d_out;

    // final_adj destination: appended after out if there is room, else fallback scratch
    float* fa;
    if (out_size >= OUT_ELEMS + NN * NN) {
        fa = out + OUT_ELEMS;
    } else {
        void* p = nullptr;
        cudaGetSymbolAddress(&p, g_fa_fb);
        fa = (float*)p;
    }

    const int smem_scores = (TILE * NN + TILE * NDm) * sizeof(float);  // ~66 KB
    cudaFuncSetAttribute(scores_topk_kernel,
                         cudaFuncAttributeMaxDynamicSharedMemorySize, smem_scores);

    zero_kernel<<<2048, 256>>>(fa);
    scores_topk_kernel<<<HH * (NN / TILE), 256, smem_scores>>>(e1, e2, temp);
    build_rows_kernel<<<NN / 8, 256>>>(ew1, eb1, ew2, eb2, fa);
    scan_kernel<<<1, 1024>>>();
    fill_kernel<<<NN, 96>>>();
    support_kernel<<<(BLT * NN) / 16, 256>>>(x, weight);
    spmm_kernel<<<NN, 256>>>(bias, out);
}

// round 3
// speedup vs baseline: 1.0096x; 1.0096x over previous
#include <cuda_runtime.h>
#include <cstdint>

#define NN   2000
#define HH   4
#define NDm  64
#define KK   20
#define TILE 8
#define BLT  128          // B*L = 4*32
#define DD   64
#define OUT_ELEMS (4*2000*32*64)
#define NNZ_CAP   (NN*80)

// ---------------- scratch (device globals; no allocation) ----------------
__device__ float g_support[(size_t)BLT*NN*DD];   // 65.5 MB
__device__ int   g_tki[HH*NN*KK];
__device__ float g_tkv[HH*NN*KK];
__device__ int   g_rowj[NN*80];
__device__ float g_rowv[NN*80];
__device__ int   g_rowcnt[NN];
__device__ int   g_colcnt[NN];
__device__ int   g_colptr[NN];
__device__ int   g_colcur[NN];
__device__ int   g_ci[NNZ_CAP];
__device__ float g_cv[NNZ_CAP];
__device__ float g_fa_fb[(size_t)NN*NN];         // fallback final_adj (16 MB)

// ---------------- 0: zero counters + final_adj region ----------------
__global__ void zero_kernel(float* fa) {
    int idx = blockIdx.x * blockDim.x + threadIdx.x;
    if (idx < NN) g_colcnt[idx] = 0;
    size_t stride = (size_t)gridDim.x * blockDim.x;
    for (size_t p = idx; p < (size_t)NN * NN; p += stride) fa[p] = 0.f;
}

// ---------------- 1: scores + softmax + top-20 ----------------
// grid = H * (N/TILE) blocks, 256 threads (8 warps; warp w owns row n0+w)
__global__ __launch_bounds__(256) void scores_topk_kernel(
    const float* __restrict__ e1, const float* __restrict__ e2,
    const float* __restrict__ temp)
{
    extern __shared__ float sm[];
    float* s   = sm;                // [TILE][NN]
    float* e1s = sm + TILE * NN;    // [TILE][NDm]

    int h  = blockIdx.x / (NN / TILE);
    int n0 = (blockIdx.x % (NN / TILE)) * TILE;
    int tid = threadIdx.x;

    for (int i = tid; i < TILE * NDm; i += blockDim.x)
        e1s[i] = e1[((size_t)h * NN + n0 + i / NDm) * NDm + (i % NDm)];
    __syncthreads();

    for (int m = tid; m < NN; m += blockDim.x) {
        float acc[TILE];
#pragma unroll
        for (int r = 0; r < TILE; r++) acc[r] = 0.f;
        const float* e2p = e2 + (size_t)h * NDm * NN + m;
#pragma unroll 8
        for (int d = 0; d < NDm; d++) {
            float b = e2p[(size_t)d * NN];
#pragma unroll
            for (int r = 0; r < TILE; r++) acc[r] = fmaf(e1s[r * NDm + d], b, acc[r]);
        }
#pragma unroll
        for (int r = 0; r < TILE; r++) s[r * NN + m] = acc[r];
    }
    __syncthreads();

    int w = tid >> 5, lane = tid & 31;
    float invT = 1.0f / temp[h];
    float* sw = s + w * NN;

    // relu + /temp in place; row max (all values >= 0)
    float M = 0.f;
    for (int m = lane; m < NN; m += 32) {
        float a = fmaxf(sw[m], 0.f) * invT;
        sw[m] = a;
        M = fmaxf(M, a);
    }
#pragma unroll
    for (int o = 16; o; o >>= 1) M = fmaxf(M, __shfl_xor_sync(0xffffffffu, M, o));

    float S = 0.f;
    for (int m = lane; m < NN; m += 32) S += __expf(sw[m] - M);
#pragma unroll
    for (int o = 16; o; o >>= 1) S += __shfl_xor_sync(0xffffffffu, S, o);

    int base = (h * NN + n0 + w) * KK;
    float ssel = 0.f;
    for (int k = 0; k < KK; k++) {
        float best = -1.f; int bi = NN;
        for (int m = lane; m < NN; m += 32) {
            float v = sw[m];
            if (v > best) { best = v; bi = m; }   // ascending m keeps lowest index on ties
        }
#pragma unroll
        for (int o = 16; o; o >>= 1) {
            float ov = __shfl_xor_sync(0xffffffffu, best, o);
            int   oi = __shfl_xor_sync(0xffffffffu, bi,   o);
            if (ov > best || (ov == best && oi < bi)) { best = ov; bi = oi; }
        }
        float e = __expf(best - M);
        ssel += e;                       // same on all lanes
        if (lane == 0) { g_tki[base + k] = bi; g_tkv[base + k] = e; }
        sw[bi] = -1.f;                   // mark taken (all lanes write same value)
        __syncwarp();
    }
    // adj_val = (e/S) / (ssel/S + 1e-8) = e / (ssel + 1e-8*S)
    float denom = ssel + 1e-8f * S;
    __syncwarp();
    if (lane < KK) g_tkv[base + lane] = g_tkv[base + lane] / denom;
}

// ---------------- 2: per-row union + edge MLP -> sparse rows + dense fa ----------------
// one warp per row i; grid = N/8 blocks of 256 threads
__global__ __launch_bounds__(256) void build_rows_kernel(
    const float* __restrict__ ew1, const float* __restrict__ eb1,
    const float* __restrict__ ew2, const float* __restrict__ eb2,
    float* __restrict__ fa)
{
    __shared__ float s_ew1[HH * 8];
    __shared__ float s_eb1[8];
    __shared__ float s_ew2[8];
    __shared__ int   s_js[8][80];
    __shared__ float s_vs[8][80];

    int tid = threadIdx.x;
    if (tid < 32) s_ew1[tid] = ew1[tid];
    else if (tid < 40) s_eb1[tid - 32] = eb1[tid - 32];
    else if (tid < 48) s_ew2[tid - 40] = ew2[tid - 40];
    float beta2 = eb2[0];
    __syncthreads();

    int w = tid >> 5, lane = tid & 31;
    int i = blockIdx.x * 8 + w;

    for (int e = lane; e < 80; e += 32) {
        int hh = e / KK, k = e % KK;
        s_js[w][e] = g_tki[(hh * NN + i) * KK + k];
        s_vs[w][e] = g_tkv[(hh * NN + i) * KK + k];
    }
    __syncwarp();

    int cnt = 0;
    for (int p = 0; p < 3; p++) {
        int e = lane + p * 32;
        bool owned = false;
        int j = -1;
        if (e < 80) {
            j = s_js[w][e];
            owned = true;
            for (int q = 0; q < e; q++)
                if (s_js[w][q] == j) { owned = false; break; }
        }
        unsigned bal = __ballot_sync(0xffffffffu, owned);
        int pos = cnt + __popc(bal & ((1u << lane) - 1u));
        if (owned) {
            float v[HH];
            float vsum = 0.f;
#pragma unroll
            for (int hh = 0; hh < HH; hh++) {
                float vv = 0.f;
                for (int k = 0; k < KK; k++)
                    if (s_js[w][hh * KK + k] == j) { vv = s_vs[w][hh * KK + k]; break; }
                v[hh] = vv; vsum += vv;
            }
            float ewv = beta2;
#pragma unroll
            for (int c = 0; c < 8; c++) {
                float hid = s_eb1[c];
#pragma unroll
                for (int hh = 0; hh < HH; hh++) hid = fmaf(v[hh], s_ew1[hh * 8 + c], hid);
                hid = fmaxf(hid, 0.f);
                ewv = fmaf(hid, s_ew2[c], ewv);
            }
            float sig  = 1.f / (1.f + __expf(-ewv));
            float favv = sig * (vsum * 0.25f);
            g_rowj[i * 80 + pos] = j;
            g_rowv[i * 80 + pos] = favv;
            atomicAdd(&g_colcnt[j], 1);
            fa[(size_t)i * NN + j] = favv;
        }
        cnt += __popc(bal);
    }
    if (lane == 0) g_rowcnt[i] = cnt;
}

// ---------------- 3: exclusive scan over column counts (single block) ----------------
__global__ __launch_bounds__(1024) void scan_kernel() {
    __shared__ int buf[1024];
    int t = threadIdx.x;
    int c0 = (2 * t     < NN) ? g_colcnt[2 * t]     : 0;
    int c1 = (2 * t + 1 < NN) ? g_colcnt[2 * t + 1] : 0;
    int psum = c0 + c1;
    buf[t] = psum;
    __syncthreads();
    for (int off = 1; off < 1024; off <<= 1) {
        int tmp = (t >= off) ? buf[t - off] : 0;
        __syncthreads();
        buf[t] += tmp;
        __syncthreads();
    }
    int base = buf[t] - psum;   // exclusive
    if (2 * t < NN)     { g_colptr[2 * t]     = base;      g_colcur[2 * t]     = base; }
    if (2 * t + 1 < NN) { g_colptr[2 * t + 1] = base + c0; g_colcur[2 * t + 1] = base + c0; }
}

// ---------------- 4: fill transposed (per-column) entry lists ----------------
__global__ void fill_kernel() {
    int i = blockIdx.x;
    int t = threadIdx.x;
    int cnt = g_rowcnt[i];
    if (t < cnt) {
        int j = g_rowj[i * 80 + t];
        int pos = atomicAdd(&g_colcur[j], 1);
        g_ci[pos] = i;
        g_cv[pos] = g_rowv[i * 80 + t];
    }
}

// ---------------- 5: support = xr @ W  (B*L x N x 64) ----------------
// block = 256 threads, 16 rows/block
__global__ __launch_bounds__(256) void support_kernel(
    const float* __restrict__ x, const float* __restrict__ W)
{
    __shared__ float Ws[64 * 64];
    __shared__ float xs[16 * 64];
    int tid = threadIdx.x;
    for (int i = tid; i < 4096; i += 256) Ws[i] = W[i];
    int row0 = blockIdx.x * 16;
    for (int i = tid; i < 16 * 64; i += 256) {
        int rr = i >> 6, d = i & 63;
        int r = row0 + rr;           // r = bl*NN + n
        int bl = r / NN, n = r % NN;
        int b = bl >> 5, l = bl & 31;
        xs[i] = x[(((size_t)(b * NN + n) * 32) + l) * 64 + d];
    }
    __syncthreads();
    int o = tid & 63, rq = tid >> 6;
    float a0 = 0.f, a1 = 0.f, a2 = 0.f, a3 = 0.f;
#pragma unroll 8
    for (int d = 0; d < 64; d++) {
        float wv = Ws[d * 64 + o];
        a0 = fmaf(xs[(rq * 4 + 0) * 64 + d], wv, a0);
        a1 = fmaf(xs[(rq * 4 + 1) * 64 + d], wv, a1);
        a2 = fmaf(xs[(rq * 4 + 2) * 64 + d], wv, a2);
        a3 = fmaf(xs[(rq * 4 + 3) * 64 + d], wv, a3);
    }
    size_t base = (size_t)(row0 + rq * 4) * 64 + o;
    g_support[base]       = a0;
    g_support[base + 64]  = a1;
    g_support[base + 128] = a2;
    g_support[base + 192] = a3;
}

// ---------------- 6: sparse out[b,c,l,:] = sum_e w_e * support[bl, j_e, :] + bias ----------------
// one block per column c; 256 threads = 16 float4-lanes x 16 bl-groups; 8 bl iters
__global__ __launch_bounds__(256) void spmm_kernel(
    const float* __restrict__ bias, float* __restrict__ out)
{
    __shared__ int   sj[512];
    __shared__ float sv[512];
    int c = blockIdx.x;
    int tid = threadIdx.x;
    int q = tid & 15;       // d = 4q .. 4q+3
    int g = tid >> 4;       // 0..15
    int start = g_colptr[c], cnt = g_colcnt[c];

    float4 acc[8];
#pragma unroll
    for (int it = 0; it < 8; it++) acc[it] = make_float4(0.f, 0.f, 0.f, 0.f);

    for (int off = 0; off < cnt; off += 512) {
        int chunk = min(512, cnt - off);
        for (int e = tid; e < chunk; e += 256) {
            sj[e] = g_ci[start + off + e];
            sv[e] = g_cv[start + off + e];
        }
        __syncthreads();
        for (int e = 0; e < chunk; e++) {
            float wv = sv[e];
            const float4* sp = (const float4*)g_support + (size_t)sj[e] * 16 + q;
#pragma unroll
            for (int it = 0; it < 8; it++) {
                int bl = it * 16 + g;
                float4 s4 = sp[(size_t)bl * (NN * 16)];
                acc[it].x = fmaf(wv, s4.x, acc[it].x);
                acc[it].y = fmaf(wv, s4.y, acc[it].y);
                acc[it].z = fmaf(wv, s4.z, acc[it].z);
                acc[it].w = fmaf(wv, s4.w, acc[it].w);
            }
        }
        __syncthreads();
    }

    float4 bv = ((const float4*)bias)[q];
#pragma unroll
    for (int it = 0; it < 8; it++) {
        int bl = it * 16 + g;
        int b = bl >> 5, l = bl & 31;
        float4 r;
        r.x = acc[it].x + bv.x;
        r.y = acc[it].y + bv.y;
        r.z = acc[it].z + bv.z;
        r.w = acc[it].w + bv.w;
        ((float4*)out)[(size_t)((b * NN + c) * 32 + l) * 16 + q] = r;
    }
}

// ---------------- launch ----------------
extern "C" void kernel_launch(void* const* d_in, const int* in_sizes, int n_in,
                              void* d_out, int out_size)
{
    const float* x      = (const float*)d_in[0];
    const float* e1     = (const float*)d_in[1];
    const float* e2     = (const float*)d_in[2];
    const float* temp   = (const float*)d_in[3];
    const float* ew1    = (const float*)d_in[4];
    const float* eb1    = (const float*)d_in[5];
    const float* ew2    = (const float*)d_in[6];
    const float* eb2    = (const float*)d_in[7];
    const float* weight = (const float*)d_in[8];
    const float* bias   = (const float*)d_in[9];
    float* out = (float*)d_out;

    // final_adj destination: appended after out if there is room, else fallback scratch
    float* fa;
    if (out_size >= OUT_ELEMS + NN * NN) {
        fa = out + OUT_ELEMS;
    } else {
        void* p = nullptr;
        cudaGetSymbolAddress(&p, g_fa_fb);
        fa = (float*)p;
    }

    const int smem_scores = (TILE * NN + TILE * NDm) * sizeof(float);  // ~66 KB
    cudaFuncSetAttribute(scores_topk_kernel,
                         cudaFuncAttributeMaxDynamicSharedMemorySize, smem_scores);

    zero_kernel<<<2048, 256>>>(fa);
    scores_topk_kernel<<<HH * (NN / TILE), 256, smem_scores>>>(e1, e2, temp);
    build_rows_kernel<<<NN / 8, 256>>>(ew1, eb1, ew2, eb2, fa);
    scan_kernel<<<1, 1024>>>();
    fill_kernel<<<NN, 96>>>();
    support_kernel<<<(BLT * NN) / 16, 256>>>(x, weight);
    spmm_kernel<<<NN, 256>>>(bias, out);
}

// round 4
// speedup vs baseline: 1.2728x; 1.2607x over previous
#include <cuda_runtime.h>
#include <cuda_fp16.h>
#include <cstdint>

#define NN   2000
#define HH   4
#define NDm  64
#define KK   20
#define TILE 8
#define BLT  128          // B*L = 4*32
#define DD   64
#define OUT_ELEMS (4*2000*32*64)
#define NNZ_CAP   (NN*80)

// ---------------- scratch (device globals; no allocation) ----------------
__device__ __align__(16) __half g_supph[(size_t)BLT*NN*DD];   // 32.8 MB fp16 support
__device__ int   g_tki[HH*NN*KK];
__device__ float g_tkv[HH*NN*KK];
__device__ int   g_rowj[NN*80];
__device__ float g_rowv[NN*80];
__device__ int   g_rowcnt[NN];
__device__ int   g_colcnt[NN];
__device__ int   g_colptr[NN];
__device__ int   g_colcur[NN];
__device__ int   g_ci[NNZ_CAP];
__device__ float g_cv[NNZ_CAP];
__device__ float g_fa_fb[(size_t)NN*NN];         // fallback final_adj (16 MB)

// ---------------- 0: zero counters + final_adj region ----------------
__global__ void zero_kernel(float* fa) {
    int idx = blockIdx.x * blockDim.x + threadIdx.x;
    if (idx < NN) g_colcnt[idx] = 0;
    size_t stride = (size_t)gridDim.x * blockDim.x;
    for (size_t p = idx; p < (size_t)NN * NN; p += stride) fa[p] = 0.f;
}

// ---------------- 1: scores + softmax + top-20 ----------------
// grid = H * (N/TILE) blocks, 256 threads (8 warps; warp w owns row n0+w)
__global__ __launch_bounds__(256) void scores_topk_kernel(
    const float* __restrict__ e1, const float* __restrict__ e2,
    const float* __restrict__ temp)
{
    extern __shared__ float sm[];
    float* s   = sm;                // [TILE][NN]
    float* e1s = sm + TILE * NN;    // [TILE][NDm]

    int h  = blockIdx.x / (NN / TILE);
    int n0 = (blockIdx.x % (NN / TILE)) * TILE;
    int tid = threadIdx.x;

    for (int i = tid; i < TILE * NDm; i += blockDim.x)
        e1s[i] = e1[((size_t)h * NN + n0 + i / NDm) * NDm + (i % NDm)];
    __syncthreads();

    for (int m = tid; m < NN; m += blockDim.x) {
        float acc[TILE];
#pragma unroll
        for (int r = 0; r < TILE; r++) acc[r] = 0.f;
        const float* e2p = e2 + (size_t)h * NDm * NN + m;
#pragma unroll 8
        for (int d = 0; d < NDm; d++) {
            float b = e2p[(size_t)d * NN];
#pragma unroll
            for (int r = 0; r < TILE; r++) acc[r] = fmaf(e1s[r * NDm + d], b, acc[r]);
        }
#pragma unroll
        for (int r = 0; r < TILE; r++) s[r * NN + m] = acc[r];
    }
    __syncthreads();

    int w = tid >> 5, lane = tid & 31;
    float invT = 1.0f / temp[h];
    float* sw = s + w * NN;

    // relu + /temp in place; row max (all values >= 0)
    float M = 0.f;
    for (int m = lane; m < NN; m += 32) {
        float a = fmaxf(sw[m], 0.f) * invT;
        sw[m] = a;
        M = fmaxf(M, a);
    }
#pragma unroll
    for (int o = 16; o; o >>= 1) M = fmaxf(M, __shfl_xor_sync(0xffffffffu, M, o));

    float S = 0.f;
    for (int m = lane; m < NN; m += 32) S += __expf(sw[m] - M);
#pragma unroll
    for (int o = 16; o; o >>= 1) S += __shfl_xor_sync(0xffffffffu, S, o);

    int base = (h * NN + n0 + w) * KK;
    float ssel = 0.f;
    for (int k = 0; k < KK; k++) {
        float best = -1.f; int bi = NN;
        for (int m = lane; m < NN; m += 32) {
            float v = sw[m];
            if (v > best) { best = v; bi = m; }   // ascending m keeps lowest index on ties
        }
#pragma unroll
        for (int o = 16; o; o >>= 1) {
            float ov = __shfl_xor_sync(0xffffffffu, best, o);
            int   oi = __shfl_xor_sync(0xffffffffu, bi,   o);
            if (ov > best || (ov == best && oi < bi)) { best = ov; bi = oi; }
        }
        float e = __expf(best - M);
        ssel += e;                       // same on all lanes
        if (lane == 0) { g_tki[base + k] = bi; g_tkv[base + k] = e; }
        sw[bi] = -1.f;                   // mark taken (all lanes write same value)
        __syncwarp();
    }
    // adj_val = (e/S) / (ssel/S + 1e-8) = e / (ssel + 1e-8*S)
    float denom = ssel + 1e-8f * S;
    __syncwarp();
    if (lane < KK) g_tkv[base + lane] = g_tkv[base + lane] / denom;
}

// ---------------- 2: per-row union + edge MLP -> sparse rows + dense fa ----------------
// one warp per row i; grid = N/8 blocks of 256 threads
__global__ __launch_bounds__(256) void build_rows_kernel(
    const float* __restrict__ ew1, const float* __restrict__ eb1,
    const float* __restrict__ ew2, const float* __restrict__ eb2,
    float* __restrict__ fa)
{
    __shared__ float s_ew1[HH * 8];
    __shared__ float s_eb1[8];
    __shared__ float s_ew2[8];
    __shared__ int   s_js[8][80];
    __shared__ float s_vs[8][80];

    int tid = threadIdx.x;
    if (tid < 32) s_ew1[tid] = ew1[tid];
    else if (tid < 40) s_eb1[tid - 32] = eb1[tid - 32];
    else if (tid < 48) s_ew2[tid - 40] = ew2[tid - 40];
    float beta2 = eb2[0];
    __syncthreads();

    int w = tid >> 5, lane = tid & 31;
    int i = blockIdx.x * 8 + w;

    for (int e = lane; e < 80; e += 32) {
        int hh = e / KK, k = e % KK;
        s_js[w][e] = g_tki[(hh * NN + i) * KK + k];
        s_vs[w][e] = g_tkv[(hh * NN + i) * KK + k];
    }
    __syncwarp();

    int cnt = 0;
    for (int p = 0; p < 3; p++) {
        int e = lane + p * 32;
        bool owned = false;
        int j = -1;
        if (e < 80) {
            j = s_js[w][e];
            owned = true;
            for (int q = 0; q < e; q++)
                if (s_js[w][q] == j) { owned = false; break; }
        }
        unsigned bal = __ballot_sync(0xffffffffu, owned);
        int pos = cnt + __popc(bal & ((1u << lane) - 1u));
        if (owned) {
            float v[HH];
            float vsum = 0.f;
#pragma unroll
            for (int hh = 0; hh < HH; hh++) {
                float vv = 0.f;
                for (int k = 0; k < KK; k++)
                    if (s_js[w][hh * KK + k] == j) { vv = s_vs[w][hh * KK + k]; break; }
                v[hh] = vv; vsum += vv;
            }
            float ewv = beta2;
#pragma unroll
            for (int c = 0; c < 8; c++) {
                float hid = s_eb1[c];
#pragma unroll
                for (int hh = 0; hh < HH; hh++) hid = fmaf(v[hh], s_ew1[hh * 8 + c], hid);
                hid = fmaxf(hid, 0.f);
                ewv = fmaf(hid, s_ew2[c], ewv);
            }
            float sig  = 1.f / (1.f + __expf(-ewv));
            float favv = sig * (vsum * 0.25f);
            g_rowj[i * 80 + pos] = j;
            g_rowv[i * 80 + pos] = favv;
            atomicAdd(&g_colcnt[j], 1);
            fa[(size_t)i * NN + j] = favv;
        }
        cnt += __popc(bal);
    }
    if (lane == 0) g_rowcnt[i] = cnt;
}

// ---------------- 3: exclusive scan over column counts (single block) ----------------
__global__ __launch_bounds__(1024) void scan_kernel() {
    __shared__ int buf[1024];
    int t = threadIdx.x;
    int c0 = (2 * t     < NN) ? g_colcnt[2 * t]     : 0;
    int c1 = (2 * t + 1 < NN) ? g_colcnt[2 * t + 1] : 0;
    int psum = c0 + c1;
    buf[t] = psum;
    __syncthreads();
    for (int off = 1; off < 1024; off <<= 1) {
        int tmp = (t >= off) ? buf[t - off] : 0;
        __syncthreads();
        buf[t] += tmp;
        __syncthreads();
    }
    int base = buf[t] - psum;   // exclusive
    if (2 * t < NN)     { g_colptr[2 * t]     = base;      g_colcur[2 * t]     = base; }
    if (2 * t + 1 < NN) { g_colptr[2 * t + 1] = base + c0; g_colcur[2 * t + 1] = base + c0; }
}

// ---------------- 4: fill transposed (per-column) entry lists ----------------
__global__ void fill_kernel() {
    int i = blockIdx.x;
    int t = threadIdx.x;
    int cnt = g_rowcnt[i];
    if (t < cnt) {
        int j = g_rowj[i * 80 + t];
        int pos = atomicAdd(&g_colcur[j], 1);
        g_ci[pos] = i;
        g_cv[pos] = g_rowv[i * 80 + t];
    }
}

// ---------------- 5: support = fp16( xr @ W )  (B*L x N x 64) ----------------
// block = 256 threads, 16 rows/block
__global__ __launch_bounds__(256) void support_kernel(
    const float* __restrict__ x, const float* __restrict__ W)
{
    __shared__ float Ws[64 * 64];
    __shared__ float xs[16 * 64];
    int tid = threadIdx.x;
    for (int i = tid; i < 4096; i += 256) Ws[i] = W[i];
    int row0 = blockIdx.x * 16;
    for (int i = tid; i < 16 * 64; i += 256) {
        int rr = i >> 6, d = i & 63;
        int r = row0 + rr;           // r = bl*NN + n
        int bl = r / NN, n = r % NN;
        int b = bl >> 5, l = bl & 31;
        xs[i] = x[(((size_t)(b * NN + n) * 32) + l) * 64 + d];
    }
    __syncthreads();
    int o = tid & 63, rq = tid >> 6;
    float a0 = 0.f, a1 = 0.f, a2 = 0.f, a3 = 0.f;
#pragma unroll 8
    for (int d = 0; d < 64; d++) {
        float wv = Ws[d * 64 + o];
        a0 = fmaf(xs[(rq * 4 + 0) * 64 + d], wv, a0);
        a1 = fmaf(xs[(rq * 4 + 1) * 64 + d], wv, a1);
        a2 = fmaf(xs[(rq * 4 + 2) * 64 + d], wv, a2);
        a3 = fmaf(xs[(rq * 4 + 3) * 64 + d], wv, a3);
    }
    size_t base = (size_t)(row0 + rq * 4) * 64 + o;
    g_supph[base]       = __float2half_rn(a0);
    g_supph[base + 64]  = __float2half_rn(a1);
    g_supph[base + 128] = __float2half_rn(a2);
    g_supph[base + 192] = __float2half_rn(a3);
}

// ---------------- 6: sparse out[b,c,l,:] = sum_e w_e * support[bl, j_e, :] + bias ----------------
// one block per column c; 256 threads = 8 d-octets x 32 bl-groups; 4 bl iters
__global__ __launch_bounds__(256) void spmm_kernel(
    const float* __restrict__ bias, float* __restrict__ out)
{
    __shared__ int   sj[512];
    __shared__ float sv[512];
    int c = blockIdx.x;
    int tid = threadIdx.x;
    int q = tid & 7;        // d octet: d = 8q .. 8q+7
    int g = tid >> 3;       // 0..31
    int start = g_colptr[c], cnt = g_colcnt[c];

    float acc[4][8];
#pragma unroll
    for (int it = 0; it < 4; it++)
#pragma unroll
        for (int j = 0; j < 8; j++) acc[it][j] = 0.f;

    const uint4* supp4 = (const uint4*)g_supph;   // 8 halves per uint4

    for (int off = 0; off < cnt; off += 512) {
        int chunk = min(512, cnt - off);
        for (int e = tid; e < chunk; e += 256) {
            sj[e] = g_ci[start + off + e];
            sv[e] = g_cv[start + off + e];
        }
        __syncthreads();
        for (int e = 0; e < chunk; e++) {
            float wv = sv[e];
            int   i  = sj[e];
#pragma unroll
            for (int it = 0; it < 4; it++) {
                int bl = it * 32 + g;
                uint4 h4 = supp4[(size_t)(bl * NN + i) * 8 + q];
                const __half2* hh = (const __half2*)&h4;
#pragma unroll
                for (int j = 0; j < 4; j++) {
                    float2 f = __half22float2(hh[j]);
                    acc[it][2 * j]     = fmaf(wv, f.x, acc[it][2 * j]);
                    acc[it][2 * j + 1] = fmaf(wv, f.y, acc[it][2 * j + 1]);
                }
            }
        }
        __syncthreads();
    }

    float bv[8];
#pragma unroll
    for (int j = 0; j < 8; j++) bv[j] = bias[q * 8 + j];

#pragma unroll
    for (int it = 0; it < 4; it++) {
        int bl = it * 32 + g;
        int b = bl >> 5, l = bl & 31;
        float4 r0, r1;
        r0.x = acc[it][0] + bv[0]; r0.y = acc[it][1] + bv[1];
        r0.z = acc[it][2] + bv[2]; r0.w = acc[it][3] + bv[3];
        r1.x = acc[it][4] + bv[4]; r1.y = acc[it][5] + bv[5];
        r1.z = acc[it][6] + bv[6]; r1.w = acc[it][7] + bv[7];
        size_t ob = (size_t)((b * NN + c) * 32 + l) * 16 + q * 2;
        ((float4*)out)[ob]     = r0;
        ((float4*)out)[ob + 1] = r1;
    }
}

// ---------------- launch ----------------
extern "C" void kernel_launch(void* const* d_in, const int* in_sizes, int n_in,
                              void* d_out, int out_size)
{
    const float* x      = (const float*)d_in[0];
    const float* e1     = (const float*)d_in[1];
    const float* e2     = (const float*)d_in[2];
    const float* temp   = (const float*)d_in[3];
    const float* ew1    = (const float*)d_in[4];
    const float* eb1    = (const float*)d_in[5];
    const float* ew2    = (const float*)d_in[6];
    const float* eb2    = (const float*)d_in[7];
    const float* weight = (const float*)d_in[8];
    const float* bias   = (const float*)d_in[9];
    float* out = (float*)d_out;

    // final_adj destination: appended after out if there is room, else fallback scratch
    float* fa;
    if (out_size >= OUT_ELEMS + NN * NN) {
        fa = out + OUT_ELEMS;
    } else {
        void* p = nullptr;
        cudaGetSymbolAddress(&p, g_fa_fb);
        fa = (float*)p;
    }

    const int smem_scores = (TILE * NN + TILE * NDm) * sizeof(float);  // ~66 KB
    cudaFuncSetAttribute(scores_topk_kernel,
                         cudaFuncAttributeMaxDynamicSharedMemorySize, smem_scores);

    zero_kernel<<<2048, 256>>>(fa);
    scores_topk_kernel<<<HH * (NN / TILE), 256, smem_scores>>>(e1, e2, temp);
    build_rows_kernel<<<NN / 8, 256>>>(ew1, eb1, ew2, eb2, fa);
    scan_kernel<<<1, 1024>>>();
    fill_kernel<<<NN, 96>>>();
    support_kernel<<<(BLT * NN) / 16, 256>>>(x, weight);
    spmm_kernel<<<NN, 256>>>(bias, out);
}

// round 5
// speedup vs baseline: 1.3870x; 1.0897x over previous
#include <cuda_runtime.h>
#include <cuda_fp16.h>
#include <cstdint>

#define NN   2000
#define HH   4
#define NDm  64
#define KK   20
#define TILE 8
#define BLT  128          // B*L = 4*32
#define DD   64
#define OUT_ELEMS (4*2000*32*64)
#define NNZ_CAP   (NN*80)

// ---------------- scratch (device globals; no allocation) ----------------
__device__ __align__(16) __half g_supph[(size_t)BLT*NN*DD];   // 32.8 MB fp16 support
__device__ int   g_tki[HH*NN*KK];
__device__ float g_tkv[HH*NN*KK];
__device__ int   g_rowj[NN*80];
__device__ float g_rowv[NN*80];
__device__ int   g_rowcnt[NN];
__device__ int   g_colcnt[NN];
__device__ int   g_colptr[NN];
__device__ int   g_colcur[NN];
__device__ int   g_ci[NNZ_CAP];
__device__ float g_cv[NNZ_CAP];
__device__ float g_fa_fb[(size_t)NN*NN];         // fallback final_adj (16 MB)

// ---------------- 0: zero counters + final_adj region ----------------
__global__ void zero_kernel(float* fa) {
    int idx = blockIdx.x * blockDim.x + threadIdx.x;
    if (idx < NN) g_colcnt[idx] = 0;
    size_t stride = (size_t)gridDim.x * blockDim.x;
    for (size_t p = idx; p < (size_t)NN * NN; p += stride) fa[p] = 0.f;
}

// ---------------- 1: scores + softmax + top-20 ----------------
// grid = H * (N/TILE) blocks, 256 threads (8 warps; warp w owns row n0+w)
__global__ __launch_bounds__(256) void scores_topk_kernel(
    const float* __restrict__ e1, const float* __restrict__ e2,
    const float* __restrict__ temp)
{
    extern __shared__ float sm[];
    float* s   = sm;                // [TILE][NN]
    float* e1s = sm + TILE * NN;    // [TILE][NDm]

    int h  = blockIdx.x / (NN / TILE);
    int n0 = (blockIdx.x % (NN / TILE)) * TILE;
    int tid = threadIdx.x;

    for (int i = tid; i < TILE * NDm; i += blockDim.x)
        e1s[i] = e1[((size_t)h * NN + n0 + i / NDm) * NDm + (i % NDm)];
    __syncthreads();

    for (int m = tid; m < NN; m += blockDim.x) {
        float acc[TILE];
#pragma unroll
        for (int r = 0; r < TILE; r++) acc[r] = 0.f;
        const float* e2p = e2 + (size_t)h * NDm * NN + m;
#pragma unroll 8
        for (int d = 0; d < NDm; d++) {
            float b = e2p[(size_t)d * NN];
#pragma unroll
            for (int r = 0; r < TILE; r++) acc[r] = fmaf(e1s[r * NDm + d], b, acc[r]);
        }
#pragma unroll
        for (int r = 0; r < TILE; r++) s[r * NN + m] = acc[r];
    }
    __syncthreads();

    int w = tid >> 5, lane = tid & 31;
    float invT = 1.0f / temp[h];
    float* sw = s + w * NN;

    // relu + /temp in place; row max (all values >= 0)
    float M = 0.f;
    for (int m = lane; m < NN; m += 32) {
        float a = fmaxf(sw[m], 0.f) * invT;
        sw[m] = a;
        M = fmaxf(M, a);
    }
#pragma unroll
    for (int o = 16; o; o >>= 1) M = fmaxf(M, __shfl_xor_sync(0xffffffffu, M, o));

    float S = 0.f;
    for (int m = lane; m < NN; m += 32) S += __expf(sw[m] - M);
#pragma unroll
    for (int o = 16; o; o >>= 1) S += __shfl_xor_sync(0xffffffffu, S, o);

    int base = (h * NN + n0 + w) * KK;
    float ssel = 0.f;
    for (int k = 0; k < KK; k++) {
        float best = -1.f; int bi = NN;
        for (int m = lane; m < NN; m += 32) {
            float v = sw[m];
            if (v > best) { best = v; bi = m; }   // ascending m keeps lowest index on ties
        }
#pragma unroll
        for (int o = 16; o; o >>= 1) {
            float ov = __shfl_xor_sync(0xffffffffu, best, o);
            int   oi = __shfl_xor_sync(0xffffffffu, bi,   o);
            if (ov > best || (ov == best && oi < bi)) { best = ov; bi = oi; }
        }
        float e = __expf(best - M);
        ssel += e;                       // same on all lanes
        if (lane == 0) { g_tki[base + k] = bi; g_tkv[base + k] = e; }
        sw[bi] = -1.f;                   // mark taken (all lanes write same value)
        __syncwarp();
    }
    // adj_val = (e/S) / (ssel/S + 1e-8) = e / (ssel + 1e-8*S)
    float denom = ssel + 1e-8f * S;
    __syncwarp();
    if (lane < KK) g_tkv[base + lane] = g_tkv[base + lane] / denom;
}

// ---------------- 2: per-row union + edge MLP -> sparse rows + dense fa ----------------
// one warp per row i; grid = N/8 blocks of 256 threads
__global__ __launch_bounds__(256) void build_rows_kernel(
    const float* __restrict__ ew1, const float* __restrict__ eb1,
    const float* __restrict__ ew2, const float* __restrict__ eb2,
    float* __restrict__ fa)
{
    __shared__ float s_ew1[HH * 8];
    __shared__ float s_eb1[8];
    __shared__ float s_ew2[8];
    __shared__ int   s_js[8][80];
    __shared__ float s_vs[8][80];

    int tid = threadIdx.x;
    if (tid < 32) s_ew1[tid] = ew1[tid];
    else if (tid < 40) s_eb1[tid - 32] = eb1[tid - 32];
    else if (tid < 48) s_ew2[tid - 40] = ew2[tid - 40];
    float beta2 = eb2[0];
    __syncthreads();

    int w = tid >> 5, lane = tid & 31;
    int i = blockIdx.x * 8 + w;

    for (int e = lane; e < 80; e += 32) {
        int hh = e / KK, k = e % KK;
        s_js[w][e] = g_tki[(hh * NN + i) * KK + k];
        s_vs[w][e] = g_tkv[(hh * NN + i) * KK + k];
    }
    __syncwarp();

    int cnt = 0;
    for (int p = 0; p < 3; p++) {
        int e = lane + p * 32;
        bool owned = false;
        int j = -1;
        if (e < 80) {
            j = s_js[w][e];
            owned = true;
            for (int q = 0; q < e; q++)
                if (s_js[w][q] == j) { owned = false; break; }
        }
        unsigned bal = __ballot_sync(0xffffffffu, owned);
        int pos = cnt + __popc(bal & ((1u << lane) - 1u));
        if (owned) {
            float v[HH];
            float vsum = 0.f;
#pragma unroll
            for (int hh = 0; hh < HH; hh++) {
                float vv = 0.f;
                for (int k = 0; k < KK; k++)
                    if (s_js[w][hh * KK + k] == j) { vv = s_vs[w][hh * KK + k]; break; }
                v[hh] = vv; vsum += vv;
            }
            float ewv = beta2;
#pragma unroll
            for (int c = 0; c < 8; c++) {
                float hid = s_eb1[c];
#pragma unroll
                for (int hh = 0; hh < HH; hh++) hid = fmaf(v[hh], s_ew1[hh * 8 + c], hid);
                hid = fmaxf(hid, 0.f);
                ewv = fmaf(hid, s_ew2[c], ewv);
            }
            float sig  = 1.f / (1.f + __expf(-ewv));
            float favv = sig * (vsum * 0.25f);
            g_rowj[i * 80 + pos] = j;
            g_rowv[i * 80 + pos] = favv;
            atomicAdd(&g_colcnt[j], 1);
            fa[(size_t)i * NN + j] = favv;
        }
        cnt += __popc(bal);
    }
    if (lane == 0) g_rowcnt[i] = cnt;
}

// ---------------- 3: exclusive scan over column counts (single block) ----------------
__global__ __launch_bounds__(1024) void scan_kernel() {
    __shared__ int buf[1024];
    int t = threadIdx.x;
    int c0 = (2 * t     < NN) ? g_colcnt[2 * t]     : 0;
    int c1 = (2 * t + 1 < NN) ? g_colcnt[2 * t + 1] : 0;
    int psum = c0 + c1;
    buf[t] = psum;
    __syncthreads();
    for (int off = 1; off < 1024; off <<= 1) {
        int tmp = (t >= off) ? buf[t - off] : 0;
        __syncthreads();
        buf[t] += tmp;
        __syncthreads();
    }
    int base = buf[t] - psum;   // exclusive
    if (2 * t < NN)     { g_colptr[2 * t]     = base;      g_colcur[2 * t]     = base; }
    if (2 * t + 1 < NN) { g_colptr[2 * t + 1] = base + c0; g_colcur[2 * t + 1] = base + c0; }
}

// ---------------- 4: fill transposed (per-column) entry lists ----------------
__global__ void fill_kernel() {
    int i = blockIdx.x;
    int t = threadIdx.x;
    int cnt = g_rowcnt[i];
    if (t < cnt) {
        int j = g_rowj[i * 80 + t];
        int pos = atomicAdd(&g_colcur[j], 1);
        g_ci[pos] = i;
        g_cv[pos] = g_rowv[i * 80 + t];
    }
}

// ---------------- 5: support = fp16( xr @ W ), register-blocked 64x64 tile ----------------
// 128 threads: thread (tr 0..7, to 0..15) computes rows {tr+8i} x cols {to*4..to*4+3}
#define XS_STRIDE 68
__global__ __launch_bounds__(128) void support_kernel(
    const float* __restrict__ x, const float* __restrict__ W)
{
    __shared__ float xs[64 * XS_STRIDE];
    __shared__ float wt[64 * XS_STRIDE];
    int tid = threadIdx.x;

    // stage W transposed: wt[o][d]
    for (int k = tid; k < 1024; k += 128) {
        int d = k >> 4, o4 = (k & 15) * 4;
        float4 w = ((const float4*)W)[k];
        wt[(o4 + 0) * XS_STRIDE + d] = w.x;
        wt[(o4 + 1) * XS_STRIDE + d] = w.y;
        wt[(o4 + 2) * XS_STRIDE + d] = w.z;
        wt[(o4 + 3) * XS_STRIDE + d] = w.w;
    }
    // stage x rows: r = bl*NN + n -> x[b, n, l, :]
    int row0 = blockIdx.x * 64;
    for (int k = tid; k < 1024; k += 128) {
        int rr = k >> 4, f4 = k & 15;
        int r = row0 + rr;
        int bl = r / NN, n = r - bl * NN;
        int b = bl >> 5, l = bl & 31;
        float4 v = ((const float4*)(x + (((size_t)(b * NN + n) * 32) + l) * 64))[f4];
        *(float4*)&xs[rr * XS_STRIDE + f4 * 4] = v;
    }
    __syncthreads();

    int tr = tid & 7, to = tid >> 3;
    float acc[8][4];
#pragma unroll
    for (int i = 0; i < 8; i++)
#pragma unroll
        for (int j = 0; j < 4; j++) acc[i][j] = 0.f;

#pragma unroll 4
    for (int d4 = 0; d4 < 64; d4 += 4) {
        float4 xv[8], wv[4];
#pragma unroll
        for (int i = 0; i < 8; i++) xv[i] = *(const float4*)&xs[(tr + 8 * i) * XS_STRIDE + d4];
#pragma unroll
        for (int j = 0; j < 4; j++) wv[j] = *(const float4*)&wt[(to * 4 + j) * XS_STRIDE + d4];
#pragma unroll
        for (int i = 0; i < 8; i++)
#pragma unroll
            for (int j = 0; j < 4; j++) {
                acc[i][j] = fmaf(xv[i].x, wv[j].x, acc[i][j]);
                acc[i][j] = fmaf(xv[i].y, wv[j].y, acc[i][j]);
                acc[i][j] = fmaf(xv[i].z, wv[j].z, acc[i][j]);
                acc[i][j] = fmaf(xv[i].w, wv[j].w, acc[i][j]);
            }
    }

    // store fp16: 8 bytes per (i): g_supph[r*64 + to*4 .. +3]
#pragma unroll
    for (int i = 0; i < 8; i++) {
        int r = row0 + tr + 8 * i;
        __half2 h0 = __floats2half2_rn(acc[i][0], acc[i][1]);
        __half2 h1 = __floats2half2_rn(acc[i][2], acc[i][3]);
        uint2 pk;
        pk.x = *(uint32_t*)&h0;
        pk.y = *(uint32_t*)&h1;
        *(uint2*)(g_supph + (size_t)r * 64 + to * 4) = pk;
    }
}

// ---------------- 6: sparse out[b,c,l,:] = sum_e w_e * support[bl, j_e, :] + bias ----------------
// one block per column c; 256 threads = 8 d-octets x 32 bl-groups; 4 bl iters
__global__ __launch_bounds__(256) void spmm_kernel(
    const float* __restrict__ bias, float* __restrict__ out)
{
    __shared__ int   sj[512];
    __shared__ float sv[512];
    int c = blockIdx.x;
    int tid = threadIdx.x;
    int q = tid & 7;        // d octet: d = 8q .. 8q+7
    int g = tid >> 3;       // 0..31
    int start = g_colptr[c], cnt = g_colcnt[c];

    float acc[4][8];
#pragma unroll
    for (int it = 0; it < 4; it++)
#pragma unroll
        for (int j = 0; j < 8; j++) acc[it][j] = 0.f;

    const uint4* supp4 = (const uint4*)g_supph;   // 8 halves per uint4

    for (int off = 0; off < cnt; off += 512) {
        int chunk = min(512, cnt - off);
        for (int e = tid; e < chunk; e += 256) {
            sj[e] = g_ci[start + off + e];
            sv[e] = g_cv[start + off + e];
        }
        __syncthreads();
        for (int e = 0; e < chunk; e++) {
            float wv = sv[e];
            int   i  = sj[e];
#pragma unroll
            for (int it = 0; it < 4; it++) {
                int bl = it * 32 + g;
                uint4 h4 = supp4[(size_t)(bl * NN + i) * 8 + q];
                const __half2* hh = (const __half2*)&h4;
#pragma unroll
                for (int j = 0; j < 4; j++) {
                    float2 f = __half22float2(hh[j]);
                    acc[it][2 * j]     = fmaf(wv, f.x, acc[it][2 * j]);
                    acc[it][2 * j + 1] = fmaf(wv, f.y, acc[it][2 * j + 1]);
                }
            }
        }
        __syncthreads();
    }

    float bv[8];
#pragma unroll
    for (int j = 0; j < 8; j++) bv[j] = bias[q * 8 + j];

#pragma unroll
    for (int it = 0; it < 4; it++) {
        int bl = it * 32 + g;
        int b = bl >> 5, l = bl & 31;
        float4 r0, r1;
        r0.x = acc[it][0] + bv[0]; r0.y = acc[it][1] + bv[1];
        r0.z = acc[it][2] + bv[2]; r0.w = acc[it][3] + bv[3];
        r1.x = acc[it][4] + bv[4]; r1.y = acc[it][5] + bv[5];
        r1.z = acc[it][6] + bv[6]; r1.w = acc[it][7] + bv[7];
        size_t ob = (size_t)((b * NN + c) * 32 + l) * 16 + q * 2;
        ((float4*)out)[ob]     = r0;
        ((float4*)out)[ob + 1] = r1;
    }
}

// ---------------- launch ----------------
extern "C" void kernel_launch(void* const* d_in, const int* in_sizes, int n_in,
                              void* d_out, int out_size)
{
    const float* x      = (const float*)d_in[0];
    const float* e1     = (const float*)d_in[1];
    const float* e2     = (const float*)d_in[2];
    const float* temp   = (const float*)d_in[3];
    const float* ew1    = (const float*)d_in[4];
    const float* eb1    = (const float*)d_in[5];
    const float* ew2    = (const float*)d_in[6];
    const float* eb2    = (const float*)d_in[7];
    const float* weight = (const float*)d_in[8];
    const float* bias   = (const float*)d_in[9];
    float* out = (float*)d_out;

    // final_adj destination: appended after out if there is room, else fallback scratch
    float* fa;
    if (out_size >= OUT_ELEMS + NN * NN) {
        fa = out + OUT_ELEMS;
    } else {
        void* p = nullptr;
        cudaGetSymbolAddress(&p, g_fa_fb);
        fa = (float*)p;
    }

    const int smem_scores = (TILE * NN + TILE * NDm) * sizeof(float);  // ~66 KB
    cudaFuncSetAttribute(scores_topk_kernel,
                         cudaFuncAttributeMaxDynamicSharedMemorySize, smem_scores);

    zero_kernel<<<2048, 256>>>(fa);
    scores_topk_kernel<<<HH * (NN / TILE), 256, smem_scores>>>(e1, e2, temp);
    build_rows_kernel<<<NN / 8, 256>>>(ew1, eb1, ew2, eb2, fa);
    scan_kernel<<<1, 1024>>>();
    fill_kernel<<<NN, 96>>>();
    support_kernel<<<(BLT * NN) / 64, 128>>>(x, weight);
    spmm_kernel<<<NN, 256>>>(bias, out);
}